// round 3
// baseline (speedup 1.0000x reference)
#include <cuda_runtime.h>

// WOS filter: per (pixel, channel) weighted order statistic over 54 values.
// Diagonal-pair rank sums with FSET (float 0/1 mask) + dual FFMA:
//   f[e] = sum_j w[j] * [mx[j] >= mx[e]]
// computed as: f[j] init = prefix_{e<=j} w[e];  per pair (e<j):
//   m = (mx[j] >= mx[e]) ? 1 : 0
//   f[e] += m * w[j];   f[j] -= m * w[e]
#define NCH   8
#define MD    54
#define HH    160
#define WW    160
#define HO    158
#define WO    158
#define LPIX  (HO * WO)

__device__ __forceinline__ float fset_ge(float a, float b) {
    float m;
    asm("set.ge.f32.f32 %0, %1, %2;" : "=f"(m) : "f"(a), "f"(b));
    return m;  // 1.0f if a >= b else 0.0f
}

__global__ __launch_bounds__(128, 3) void WOS_72842645340328_kernel(
    const float* __restrict__ x,
    const float* __restrict__ weight,
    const float* __restrict__ bias,
    const float* __restrict__ mask,
    float* __restrict__ out)
{
    int i = blockIdx.x * blockDim.x + threadIdx.x;

    // out flat index i = n*NCH + c  (raw reinterpret in reference)
    int c  = i & 7;
    int n  = i >> 3;
    int b  = n / LPIX;
    int l  = n - b * LPIX;
    int ho = l / WO;
    int wo = l - ho * WO;

    const float* xb = x + ((b * 3) * HH + ho) * WW + wo;
    const float* mk = mask   + c * MD;
    const float* wt = weight + c * MD;

    float mx[MD];
    float w[MD];

    // Gather 3x3x3 patch; feature d = ch*9 + kh*3 + kw (torch Unfold order).
#pragma unroll
    for (int ch = 0; ch < 3; ++ch)
#pragma unroll
        for (int kh = 0; kh < 3; ++kh)
#pragma unroll
            for (int kw = 0; kw < 3; ++kw) {
                float v = __ldg(xb + (ch * HH + kh) * WW + kw);
                int d = ch * 9 + kh * 3 + kw;
                mx[d]      = v + __ldg(mk + d);
                mx[27 + d] = __ldg(mk + 27 + d) - v;
            }

#pragma unroll
    for (int j = 0; j < MD; ++j) w[j] = __ldg(wt + j);

    float Bc = __ldg(bias + c);

    // f[j] init = prefix sum of w[0..j]  (self term + all potential "smaller
    // index loses" contributions; pair loop subtracts the ones that don't apply)
    float f[MD];
    {
        float acc = 0.f;
#pragma unroll
        for (int j = 0; j < MD; ++j) { acc += w[j]; f[j] = acc; }
    }

#pragma unroll
    for (int e = 0; e < MD; ++e) {
#pragma unroll
        for (int j = e + 1; j < MD; ++j) {
            float m = fset_ge(mx[j], mx[e]);       // alu: FSET
            f[e] = fmaf(m,  w[j], f[e]);           // fma
            f[j] = fmaf(m, -w[e], f[j]);           // fma
        }
    }

    // best = min{ mx_e : f[e] <= Bc } (else +inf), maxv = max(mx) — tree reductions
    float sel[MD];
    float mxv[MD];
#pragma unroll
    for (int e = 0; e < MD; ++e) {
        sel[e] = (f[e] <= Bc) ? mx[e] : __int_as_float(0x7f800000);
        mxv[e] = mx[e];
    }
    // pad-free tree over 54: reduce 54 -> 27 -> 14 -> 7 -> 4 -> 2 -> 1
#pragma unroll
    for (int len = MD; len > 1; len = (len + 1) >> 1) {
        int half = (len + 1) >> 1;
#pragma unroll
        for (int k = 0; k + half < len; ++k) {
            sel[k] = fminf(sel[k], sel[k + half]);
            mxv[k] = fmaxf(mxv[k], mxv[k + half]);
        }
    }

    out[i] = (sel[0] <= 3.0e38f) ? sel[0] : mxv[0];
}

extern "C" void kernel_launch(void* const* d_in, const int* in_sizes, int n_in,
                              void* d_out, int out_size)
{
    const float* x      = (const float*)d_in[0];
    const float* weight = (const float*)d_in[1];
    const float* bias   = (const float*)d_in[2];
    const float* mask   = (const float*)d_in[3];
    float* out = (float*)d_out;

    // out_size = 4*8*158*158 = 798848 = 6241 * 128 exactly
    WOS_72842645340328_kernel<<<798848 / 128, 128>>>(x, weight, bias, mask, out);
}

// round 5
// speedup vs baseline: 1.2491x; 1.2491x over previous
#include <cuda_runtime.h>

// WOS filter, channel-per-block layout:
//   blockIdx.y = output channel c (weights/mask/bias warp-uniform -> UR file)
//   blockIdx.x * 128 + tid = pixel task n (coalesced x access)
// Diagonal-pair rank sums (each unordered pair compared once):
//   f[e] init = w[e]  (self term)
//   pair (e<j): p = (mx[j] >= mx[e]);  @p f[e]+=w[j];  @!p f[j]+=w[e]
// answer = min{ mx_e : f[e] <= bias } else max(mx)
#define NCH   8
#define MD    54
#define HH    160
#define WW    160
#define HO    158
#define WO    158
#define LPIX  (HO * WO)
#define NPIX  (4 * LPIX)          // 99856 pixel tasks per channel

__global__ __launch_bounds__(128, 4) void WOS_72842645340328_kernel(
    const float* __restrict__ x,
    const float* __restrict__ weight,
    const float* __restrict__ bias,
    const float* __restrict__ mask,
    float* __restrict__ out)
{
    const int c = blockIdx.y;                       // warp-uniform channel
    const int n = blockIdx.x * 128 + threadIdx.x;   // pixel task id
    if (n >= NPIX) return;

    int b  = n / LPIX;
    int l  = n - b * LPIX;
    int ho = l / WO;
    int wo = l - ho * WO;

    // Per-channel constants: uniform addresses -> uniform loads (UR file)
    const float* wt = weight + c * MD;
    const float* mk = mask   + c * MD;
    float w[MD];
#pragma unroll
    for (int j = 0; j < MD; ++j) w[j] = wt[j];
    float mkr[MD];
#pragma unroll
    for (int j = 0; j < MD; ++j) mkr[j] = mk[j];
    const float Bc = bias[c];

    const float* xb = x + ((b * 3) * HH + ho) * WW + wo;

    float mx[MD];
    // Gather 3x3x3 patch; feature d = ch*9 + kh*3 + kw (torch Unfold order).
#pragma unroll
    for (int ch = 0; ch < 3; ++ch)
#pragma unroll
        for (int kh = 0; kh < 3; ++kh)
#pragma unroll
            for (int kw = 0; kw < 3; ++kw) {
                float v = __ldg(xb + (ch * HH + kh) * WW + kw);
                int d = ch * 9 + kh * 3 + kw;
                mx[d]      = v + mkr[d];
                mx[27 + d] = mkr[27 + d] - v;
            }

    // f[e] = sum_j w[j] * [mx[j] >= mx[e]]; self term w[e]
    float f[MD];
#pragma unroll
    for (int e = 0; e < MD; ++e) f[e] = w[e];

#pragma unroll
    for (int e = 0; e < MD; ++e) {
#pragma unroll
        for (int j = e + 1; j < MD; ++j) {
            bool p = (mx[j] >= mx[e]);
            if (p)  f[e] += w[j];
            if (!p) f[j] += w[e];
        }
    }

    // best = min{ mx_e : f[e] <= Bc } (else +inf), maxv = max(mx); tree-reduce
    float sel[MD];
    float mxv[MD];
#pragma unroll
    for (int e = 0; e < MD; ++e) {
        sel[e] = (f[e] <= Bc) ? mx[e] : __int_as_float(0x7f800000);
        mxv[e] = mx[e];
    }
#pragma unroll
    for (int len = MD; len > 1; len = (len + 1) >> 1) {
        int half = (len + 1) >> 1;
#pragma unroll
        for (int k = 0; k + half < len; ++k) {
            sel[k] = fminf(sel[k], sel[k + half]);
            mxv[k] = fmaxf(mxv[k], mxv[k + half]);
        }
    }

    out[n * NCH + c] = (sel[0] <= 3.0e38f) ? sel[0] : mxv[0];
}

extern "C" void kernel_launch(void* const* d_in, const int* in_sizes, int n_in,
                              void* d_out, int out_size)
{
    const float* x      = (const float*)d_in[0];
    const float* weight = (const float*)d_in[1];
    const float* bias   = (const float*)d_in[2];
    const float* mask   = (const float*)d_in[3];
    float* out = (float*)d_out;

    dim3 grid((NPIX + 127) / 128, NCH);
    WOS_72842645340328_kernel<<<grid, 128>>>(x, weight, bias, mask, out);
}